// round 2
// baseline (speedup 1.0000x reference)
#include <cuda_runtime.h>

#define N_NODES 50000
#define N_EDGES 800000
#define IN_DIM 64
#define HID_DIM 128
#define OUT_DIM 40

// ---------------- scratch (device globals; no allocation) ----------------
__device__ int   g_cnt[N_NODES];
__device__ int   g_rowptr[N_NODES + 1];
__device__ int   g_cursor[N_NODES];
__device__ int   g_col[N_EDGES];
__device__ float g_mean1[N_NODES * IN_DIM];
__device__ float g_h[N_NODES * HID_DIM];
__device__ float g_mean2[N_NODES * HID_DIM];

// ---------------- CSR build ----------------
__global__ void k_zero_cnt() {
    int i = blockIdx.x * blockDim.x + threadIdx.x;
    if (i < N_NODES) g_cnt[i] = 0;
}

// edge_index is int32 on device (JAX default config downcasts int64 -> int32)
__global__ void k_degree(const int* __restrict__ ei) {
    int i = blockIdx.x * blockDim.x + threadIdx.x;
    if (i < N_EDGES) {
        int d = ei[N_EDGES + i];
        atomicAdd(&g_cnt[d], 1);
    }
}

// single-block exclusive scan over g_cnt -> g_rowptr, g_cursor
__global__ void k_scan() {
    __shared__ int warp_sums[32];
    __shared__ int s_carry;
    int tid = threadIdx.x;
    int lane = tid & 31, warp = tid >> 5;
    if (tid == 0) s_carry = 0;
    __syncthreads();
    for (int base = 0; base < N_NODES; base += 1024) {
        int i = base + tid;
        int v = (i < N_NODES) ? g_cnt[i] : 0;
        int x = v;
        #pragma unroll
        for (int off = 1; off < 32; off <<= 1) {
            int t = __shfl_up_sync(0xffffffffu, x, off);
            if (lane >= off) x += t;
        }
        if (lane == 31) warp_sums[warp] = x;
        __syncthreads();
        if (warp == 0) {
            int s = warp_sums[lane];
            #pragma unroll
            for (int off = 1; off < 32; off <<= 1) {
                int t = __shfl_up_sync(0xffffffffu, s, off);
                if (lane >= off) s += t;
            }
            warp_sums[lane] = s;
        }
        __syncthreads();
        int warp_off = (warp > 0) ? warp_sums[warp - 1] : 0;
        int excl = s_carry + warp_off + x - v;
        if (i < N_NODES) { g_rowptr[i] = excl; g_cursor[i] = excl; }
        __syncthreads();
        if (tid == 0) s_carry += warp_sums[31];
        __syncthreads();
    }
    if (tid == 0) g_rowptr[N_NODES] = s_carry;
}

__global__ void k_fill(const int* __restrict__ ei) {
    int i = blockIdx.x * blockDim.x + threadIdx.x;
    if (i < N_EDGES) {
        int s = ei[i];
        int d = ei[N_EDGES + i];
        int pos = atomicAdd(&g_cursor[d], 1);
        g_col[pos] = s;
    }
}

// ---------------- aggregation (warp per node, mean over neighbors) ----------------
__global__ void k_agg1(const float* __restrict__ x) {
    int node = (blockIdx.x * blockDim.x + threadIdx.x) >> 5;
    int lane = threadIdx.x & 31;
    if (node >= N_NODES) return;
    int s = g_rowptr[node], e = g_rowptr[node + 1];
    const float2* xp = (const float2*)x;
    float2 acc = make_float2(0.f, 0.f);
    for (int j = s; j < e; j++) {
        int c = g_col[j];
        float2 v = xp[c * 32 + lane];
        acc.x += v.x; acc.y += v.y;
    }
    float inv = 1.0f / (float)max(e - s, 1);
    float2 r = make_float2(acc.x * inv, acc.y * inv);
    ((float2*)g_mean1)[node * 32 + lane] = r;
}

__global__ void k_agg2() {
    int node = (blockIdx.x * blockDim.x + threadIdx.x) >> 5;
    int lane = threadIdx.x & 31;
    if (node >= N_NODES) return;
    int s = g_rowptr[node], e = g_rowptr[node + 1];
    const float4* hp = (const float4*)g_h;
    float4 acc = make_float4(0.f, 0.f, 0.f, 0.f);
    for (int j = s; j < e; j++) {
        int c = g_col[j];
        float4 v = hp[c * 32 + lane];
        acc.x += v.x; acc.y += v.y; acc.z += v.z; acc.w += v.w;
    }
    float inv = 1.0f / (float)max(e - s, 1);
    float4 r = make_float4(acc.x * inv, acc.y * inv, acc.z * inv, acc.w * inv);
    ((float4*)g_mean2)[node * 32 + lane] = r;
}

// ---------------- layer-1 GEMM: h = relu(mean1 @ Wl^T + b + x @ Wr^T) ----------------
// 64 nodes per block, 256 threads. smem: s_dat[128][65] | Wl 128x64 | Wr 128x64 | bias
#define G1_SMEM_FLOATS (128 * 65 + 8192 + 8192 + 128)
__global__ void __launch_bounds__(256) k_gemm1(
    const float* __restrict__ x, const float* __restrict__ Wl,
    const float* __restrict__ bl, const float* __restrict__ Wr)
{
    extern __shared__ float sm[];
    float* s_dat = sm;                   // 128*65 (k-major node features; reused as s_out)
    float* s_wl  = sm + 128 * 65;        // 8192
    float* s_wr  = s_wl + 8192;          // 8192
    float* s_b   = s_wr + 8192;          // 128
    int tid = threadIdx.x;
    int n0 = blockIdx.x * 64;
    int rem = min(64, N_NODES - n0);

    for (int idx = tid; idx < 8192; idx += 256) { s_wl[idx] = Wl[idx]; s_wr[idx] = Wr[idx]; }
    if (tid < 128) s_b[tid] = bl[tid];

    for (int idx = tid; idx < 64 * 128; idx += 256) {
        int l = idx >> 7, k = idx & 127;
        float v = 0.f;
        if (l < rem) {
            int node = n0 + l;
            v = (k < 64) ? g_mean1[node * 64 + k] : x[node * 64 + (k - 64)];
        }
        s_dat[k * 65 + l] = v;
    }
    __syncthreads();

    int l = tid & 63;
    int obase = (tid >> 6) * 32;
    float acc[32];
    #pragma unroll
    for (int j = 0; j < 32; j++) acc[j] = 0.f;
    const float4* wl4 = (const float4*)s_wl;
    const float4* wr4 = (const float4*)s_wr;

    for (int k = 0; k < 64; k += 4) {
        float m0 = s_dat[(k + 0) * 65 + l];
        float m1 = s_dat[(k + 1) * 65 + l];
        float m2 = s_dat[(k + 2) * 65 + l];
        float m3 = s_dat[(k + 3) * 65 + l];
        float y0 = s_dat[(64 + k + 0) * 65 + l];
        float y1 = s_dat[(64 + k + 1) * 65 + l];
        float y2 = s_dat[(64 + k + 2) * 65 + l];
        float y3 = s_dat[(64 + k + 3) * 65 + l];
        int kq = k >> 2;
        #pragma unroll
        for (int j = 0; j < 32; j++) {
            float4 a = wl4[(obase + j) * 16 + kq];
            float4 b = wr4[(obase + j) * 16 + kq];
            acc[j] += m0 * a.x + m1 * a.y + m2 * a.z + m3 * a.w
                    + y0 * b.x + y1 * b.y + y2 * b.z + y3 * b.w;
        }
    }
    __syncthreads();   // done reading s_dat; reuse as s_out
    #pragma unroll
    for (int j = 0; j < 32; j++) {
        int o = obase + j;
        s_dat[o * 65 + l] = fmaxf(acc[j] + s_b[o], 0.f);
    }
    __syncthreads();
    for (int idx = tid; idx < rem * 128; idx += 256) {
        int node = idx >> 7, o = idx & 127;
        g_h[(n0 + node) * 128 + o] = s_dat[o * 65 + node];
    }
}

// ---------------- layer-2 GEMM + relu + log_softmax + transposed write ----------------
// 64 nodes per block, 256 threads.
// smem: s_dat[256][65] | Wl2 40x128 | Wr2 40x128 | bias 40 | s_out[40][65]
#define G2_SMEM_FLOATS (256 * 65 + 5120 + 5120 + 40 + 40 * 65)
__global__ void __launch_bounds__(256) k_gemm2(
    const float* __restrict__ Wl, const float* __restrict__ bl,
    const float* __restrict__ Wr, float* __restrict__ out)
{
    extern __shared__ float sm[];
    float* s_dat = sm;                     // 256*65
    float* s_wl  = sm + 256 * 65;          // 5120
    float* s_wr  = s_wl + 5120;            // 5120
    float* s_b   = s_wr + 5120;            // 40
    float* s_out = s_b + 40;               // 40*65
    int tid = threadIdx.x;
    int n0 = blockIdx.x * 64;
    int rem = min(64, N_NODES - n0);

    for (int idx = tid; idx < 5120; idx += 256) { s_wl[idx] = Wl[idx]; s_wr[idx] = Wr[idx]; }
    if (tid < 40) s_b[tid] = bl[tid];

    for (int idx = tid; idx < 64 * 256; idx += 256) {
        int l = idx >> 8, k = idx & 255;
        float v = 0.f;
        if (l < rem) {
            int node = n0 + l;
            v = (k < 128) ? g_mean2[node * 128 + k] : g_h[node * 128 + (k - 128)];
        }
        s_dat[k * 65 + l] = v;
    }
    __syncthreads();

    int l = tid & 63;
    int obase = (tid >> 6) * 10;
    float acc[10];
    #pragma unroll
    for (int j = 0; j < 10; j++) acc[j] = 0.f;
    const float4* wl4 = (const float4*)s_wl;
    const float4* wr4 = (const float4*)s_wr;

    for (int k = 0; k < 128; k += 4) {
        float m0 = s_dat[(k + 0) * 65 + l];
        float m1 = s_dat[(k + 1) * 65 + l];
        float m2 = s_dat[(k + 2) * 65 + l];
        float m3 = s_dat[(k + 3) * 65 + l];
        float y0 = s_dat[(128 + k + 0) * 65 + l];
        float y1 = s_dat[(128 + k + 1) * 65 + l];
        float y2 = s_dat[(128 + k + 2) * 65 + l];
        float y3 = s_dat[(128 + k + 3) * 65 + l];
        int kq = k >> 2;
        #pragma unroll
        for (int j = 0; j < 10; j++) {
            float4 a = wl4[(obase + j) * 32 + kq];
            float4 b = wr4[(obase + j) * 32 + kq];
            acc[j] += m0 * a.x + m1 * a.y + m2 * a.z + m3 * a.w
                    + y0 * b.x + y1 * b.y + y2 * b.z + y3 * b.w;
        }
    }
    #pragma unroll
    for (int j = 0; j < 10; j++) {
        int o = obase + j;
        s_out[o * 65 + l] = fmaxf(acc[j] + s_b[o], 0.f);
    }
    __syncthreads();

    // per-node log_softmax over the 40 classes; coalesced transposed write
    if (tid < rem) {
        float v[OUT_DIM];
        float mx = -1e30f;
        #pragma unroll
        for (int o = 0; o < OUT_DIM; o++) { v[o] = s_out[o * 65 + tid]; mx = fmaxf(mx, v[o]); }
        float ssum = 0.f;
        #pragma unroll
        for (int o = 0; o < OUT_DIM; o++) ssum += expf(v[o] - mx);
        float lse = mx + logf(ssum);
        #pragma unroll
        for (int o = 0; o < OUT_DIM; o++) out[o * N_NODES + n0 + tid] = v[o] - lse;
    }
}

// ---------------- launcher ----------------
extern "C" void kernel_launch(void* const* d_in, const int* in_sizes, int n_in,
                              void* d_out, int out_size) {
    const float* x   = (const float*)d_in[0];
    const int*   ei  = (const int*)d_in[1];     // int32 (JAX downcasts int64)
    const float* Wl1 = (const float*)d_in[2];
    const float* bl1 = (const float*)d_in[3];
    const float* Wr1 = (const float*)d_in[4];
    const float* Wl2 = (const float*)d_in[5];
    const float* bl2 = (const float*)d_in[6];
    const float* Wr2 = (const float*)d_in[7];
    float* out = (float*)d_out;

    cudaFuncSetAttribute(k_gemm1, cudaFuncAttributeMaxDynamicSharedMemorySize,
                         G1_SMEM_FLOATS * (int)sizeof(float));
    cudaFuncSetAttribute(k_gemm2, cudaFuncAttributeMaxDynamicSharedMemorySize,
                         G2_SMEM_FLOATS * (int)sizeof(float));

    k_zero_cnt<<<(N_NODES + 255) / 256, 256>>>();
    k_degree<<<(N_EDGES + 255) / 256, 256>>>(ei);
    k_scan<<<1, 1024>>>();
    k_fill<<<(N_EDGES + 255) / 256, 256>>>(ei);
    // warp per node: 8 nodes per 256-thread block
    k_agg1<<<(N_NODES + 7) / 8, 256>>>(x);
    k_gemm1<<<(N_NODES + 63) / 64, 256, G1_SMEM_FLOATS * sizeof(float)>>>(x, Wl1, bl1, Wr1);
    k_agg2<<<(N_NODES + 7) / 8, 256>>>();
    k_gemm2<<<(N_NODES + 63) / 64, 256, G2_SMEM_FLOATS * sizeof(float)>>>(Wl2, bl2, Wr2, out);
}

// round 3
// speedup vs baseline: 1.5232x; 1.5232x over previous
#include <cuda_runtime.h>

#define N_NODES 50000
#define N_EDGES 800000
#define IN_DIM 64
#define HID_DIM 128
#define OUT_DIM 40
#define NB_SCAN 49   // ceil(50000/1024)

// ---------------- scratch (device globals; no allocation) ----------------
__device__ int   g_cnt[N_NODES];
__device__ int   g_rowptr[N_NODES + 1];
__device__ int   g_cursor[N_NODES];
__device__ int   g_col[N_EDGES];
__device__ int   g_bsum[NB_SCAN];
__device__ int   g_boff[NB_SCAN + 1];
__device__ float g_mean1[N_NODES * IN_DIM];
__device__ float g_h[N_NODES * HID_DIM];
__device__ float g_hl[N_NODES * OUT_DIM];   // h @ Wl2^T (pre-aggregation)
__device__ float g_hr[N_NODES * OUT_DIM];   // h @ Wr2^T
__device__ float g_aggl[N_NODES * OUT_DIM]; // mean-aggregated hl

// ---------------- CSR build ----------------
__global__ void k_zero_cnt() {
    int i = blockIdx.x * blockDim.x + threadIdx.x;
    if (i < N_NODES) g_cnt[i] = 0;
}

__global__ void k_degree(const int* __restrict__ ei) {
    int i = blockIdx.x * blockDim.x + threadIdx.x;
    if (i < N_EDGES) atomicAdd(&g_cnt[ei[N_EDGES + i]], 1);
}

// phase 1: per-block (1024 elems) exclusive scan; block totals to g_bsum
__global__ void __launch_bounds__(1024) k_scan_part() {
    __shared__ int wsum[32];
    int tid = threadIdx.x, lane = tid & 31, warp = tid >> 5;
    int i = blockIdx.x * 1024 + tid;
    int v = (i < N_NODES) ? g_cnt[i] : 0;
    int xs = v;
    #pragma unroll
    for (int off = 1; off < 32; off <<= 1) {
        int t = __shfl_up_sync(0xffffffffu, xs, off);
        if (lane >= off) xs += t;
    }
    if (lane == 31) wsum[warp] = xs;
    __syncthreads();
    if (warp == 0) {
        int s = wsum[lane];
        #pragma unroll
        for (int off = 1; off < 32; off <<= 1) {
            int t = __shfl_up_sync(0xffffffffu, s, off);
            if (lane >= off) s += t;
        }
        wsum[lane] = s;
    }
    __syncthreads();
    int woff = (warp > 0) ? wsum[warp - 1] : 0;
    if (i < N_NODES) g_rowptr[i] = woff + xs - v;   // local exclusive
    if (tid == 1023) g_bsum[blockIdx.x] = woff + xs;
}

// phase 2: scan the 49 block sums (smem serial — tiny)
__global__ void k_scan_bsum() {
    __shared__ int sh[NB_SCAN + 1];
    int tid = threadIdx.x;
    if (tid < NB_SCAN) sh[tid] = g_bsum[tid];
    __syncthreads();
    if (tid == 0) {
        int run = 0;
        for (int i = 0; i < NB_SCAN; i++) { int t = sh[i]; sh[i] = run; run += t; }
        sh[NB_SCAN] = run;
    }
    __syncthreads();
    if (tid <= NB_SCAN) g_boff[tid] = sh[tid];
}

// phase 3: add block offsets, init cursor, set rowptr[N]
__global__ void k_scan_add() {
    int i = blockIdx.x * blockDim.x + threadIdx.x;
    if (i < N_NODES) {
        int r = g_rowptr[i] + g_boff[i >> 10];
        g_rowptr[i] = r;
        g_cursor[i] = r;
    }
    if (i == 0) g_rowptr[N_NODES] = g_boff[NB_SCAN];
}

__global__ void k_fill(const int* __restrict__ ei) {
    int i = blockIdx.x * blockDim.x + threadIdx.x;
    if (i < N_EDGES) {
        int s = ei[i];
        int d = ei[N_EDGES + i];
        g_col[atomicAdd(&g_cursor[d], 1)] = s;
    }
}

// ---------------- layer-1 aggregation: mean over x (64-d), warp/node ----------------
__global__ void k_agg1(const float* __restrict__ x) {
    int node = (blockIdx.x * blockDim.x + threadIdx.x) >> 5;
    int lane = threadIdx.x & 31;
    if (node >= N_NODES) return;
    int s = g_rowptr[node], e = g_rowptr[node + 1];
    const float2* xp = (const float2*)x;
    float2 acc = make_float2(0.f, 0.f);
    for (int base = s; base < e; base += 32) {
        int j = base + lane;
        int myc = (j < e) ? g_col[j] : 0;
        int cnt = min(32, e - base);
        int jj = 0;
        for (; jj + 4 <= cnt; jj += 4) {
            int c0 = __shfl_sync(0xffffffffu, myc, jj);
            int c1 = __shfl_sync(0xffffffffu, myc, jj + 1);
            int c2 = __shfl_sync(0xffffffffu, myc, jj + 2);
            int c3 = __shfl_sync(0xffffffffu, myc, jj + 3);
            float2 v0 = xp[c0 * 32 + lane];
            float2 v1 = xp[c1 * 32 + lane];
            float2 v2 = xp[c2 * 32 + lane];
            float2 v3 = xp[c3 * 32 + lane];
            acc.x += (v0.x + v1.x) + (v2.x + v3.x);
            acc.y += (v0.y + v1.y) + (v2.y + v3.y);
        }
        for (; jj < cnt; jj++) {
            int c = __shfl_sync(0xffffffffu, myc, jj);
            float2 v = xp[c * 32 + lane];
            acc.x += v.x; acc.y += v.y;
        }
    }
    float inv = 1.0f / (float)max(e - s, 1);
    ((float2*)g_mean1)[node * 32 + lane] = make_float2(acc.x * inv, acc.y * inv);
}

// ---------------- layer-1 GEMM: h = relu(mean1 @ Wl^T + b + x @ Wr^T) ----------------
#define G1_SMEM_FLOATS (128 * 65 + 8192 + 8192 + 128)
__global__ void __launch_bounds__(256) k_gemm1(
    const float* __restrict__ x, const float* __restrict__ Wl,
    const float* __restrict__ bl, const float* __restrict__ Wr)
{
    extern __shared__ float sm[];
    float* s_dat = sm;                   // 128*65 k-major; reused as s_out
    float* s_wl  = sm + 128 * 65;
    float* s_wr  = s_wl + 8192;
    float* s_b   = s_wr + 8192;
    int tid = threadIdx.x;
    int n0 = blockIdx.x * 64;
    int rem = min(64, N_NODES - n0);

    for (int idx = tid; idx < 8192; idx += 256) { s_wl[idx] = Wl[idx]; s_wr[idx] = Wr[idx]; }
    if (tid < 128) s_b[tid] = bl[tid];

    for (int idx = tid; idx < 64 * 128; idx += 256) {
        int l = idx >> 7, k = idx & 127;
        float v = 0.f;
        if (l < rem) {
            int node = n0 + l;
            v = (k < 64) ? g_mean1[node * 64 + k] : x[node * 64 + (k - 64)];
        }
        s_dat[k * 65 + l] = v;
    }
    __syncthreads();

    int l = tid & 63;
    int obase = (tid >> 6) * 32;
    float acc[32];
    #pragma unroll
    for (int j = 0; j < 32; j++) acc[j] = 0.f;
    const float4* wl4 = (const float4*)s_wl;
    const float4* wr4 = (const float4*)s_wr;

    for (int k = 0; k < 64; k += 4) {
        float m0 = s_dat[(k + 0) * 65 + l];
        float m1 = s_dat[(k + 1) * 65 + l];
        float m2 = s_dat[(k + 2) * 65 + l];
        float m3 = s_dat[(k + 3) * 65 + l];
        float y0 = s_dat[(64 + k + 0) * 65 + l];
        float y1 = s_dat[(64 + k + 1) * 65 + l];
        float y2 = s_dat[(64 + k + 2) * 65 + l];
        float y3 = s_dat[(64 + k + 3) * 65 + l];
        int kq = k >> 2;
        #pragma unroll
        for (int j = 0; j < 32; j++) {
            float4 a = wl4[(obase + j) * 16 + kq];
            float4 b = wr4[(obase + j) * 16 + kq];
            acc[j] += m0 * a.x + m1 * a.y + m2 * a.z + m3 * a.w
                    + y0 * b.x + y1 * b.y + y2 * b.z + y3 * b.w;
        }
    }
    __syncthreads();
    #pragma unroll
    for (int j = 0; j < 32; j++) {
        int o = obase + j;
        s_dat[o * 65 + l] = fmaxf(acc[j] + s_b[o], 0.f);
    }
    __syncthreads();
    for (int idx = tid; idx < rem * 128; idx += 256) {
        int node = idx >> 7, o = idx & 127;
        g_h[(n0 + node) * 128 + o] = s_dat[o * 65 + node];
    }
}

// ---------------- layer-2 dual GEMM: hl = h@Wl2^T, hr = h@Wr2^T (reads h once) ----------------
#define G2AB_SMEM_FLOATS (128 * 65 + 80 * 128)
__global__ void __launch_bounds__(256) k_gemm2ab(
    const float* __restrict__ Wl, const float* __restrict__ Wr)
{
    extern __shared__ float sm[];
    float* s_dat = sm;              // 128*65 (h k-major); reused as s_out[80][65]
    float* s_w   = sm + 128 * 65;   // rows 0..39 = Wl2, rows 40..79 = Wr2
    int tid = threadIdx.x;
    int n0 = blockIdx.x * 64;
    int rem = min(64, N_NODES - n0);

    for (int idx = tid; idx < 5120; idx += 256) {
        s_w[idx] = Wl[idx];
        s_w[5120 + idx] = Wr[idx];
    }
    for (int idx = tid; idx < 64 * 128; idx += 256) {
        int l = idx >> 7, k = idx & 127;
        s_dat[k * 65 + l] = (l < rem) ? g_h[(n0 + l) * 128 + k] : 0.f;
    }
    __syncthreads();

    int l = tid & 63;
    int obase = (tid >> 6) * 20;
    float acc[20];
    #pragma unroll
    for (int j = 0; j < 20; j++) acc[j] = 0.f;
    const float4* w4 = (const float4*)s_w;

    for (int k = 0; k < 128; k += 4) {
        float h0 = s_dat[(k + 0) * 65 + l];
        float h1 = s_dat[(k + 1) * 65 + l];
        float h2 = s_dat[(k + 2) * 65 + l];
        float h3 = s_dat[(k + 3) * 65 + l];
        int kq = k >> 2;
        #pragma unroll
        for (int j = 0; j < 20; j++) {
            float4 a = w4[(obase + j) * 32 + kq];
            acc[j] += h0 * a.x + h1 * a.y + h2 * a.z + h3 * a.w;
        }
    }
    __syncthreads();
    #pragma unroll
    for (int j = 0; j < 20; j++) s_dat[(obase + j) * 65 + l] = acc[j];
    __syncthreads();
    for (int idx = tid; idx < rem * 40; idx += 256) {
        int n = idx / 40, o = idx % 40;
        g_hl[(n0 + n) * 40 + o] = s_dat[o * 65 + n];
        g_hr[(n0 + n) * 40 + o] = s_dat[(40 + o) * 65 + n];
    }
}

// ---------------- layer-2 aggregation: mean over hl (40-d), warp/node ----------------
__global__ void k_aggl() {
    int node = (blockIdx.x * blockDim.x + threadIdx.x) >> 5;
    int lane = threadIdx.x & 31;
    if (node >= N_NODES) return;
    int s = g_rowptr[node], e = g_rowptr[node + 1];
    float acc0 = 0.f, acc1 = 0.f;
    for (int base = s; base < e; base += 32) {
        int j = base + lane;
        int myc = (j < e) ? g_col[j] : 0;
        int cnt = min(32, e - base);
        int jj = 0;
        for (; jj + 4 <= cnt; jj += 4) {
            int c0 = __shfl_sync(0xffffffffu, myc, jj);
            int c1 = __shfl_sync(0xffffffffu, myc, jj + 1);
            int c2 = __shfl_sync(0xffffffffu, myc, jj + 2);
            int c3 = __shfl_sync(0xffffffffu, myc, jj + 3);
            float a0 = g_hl[c0 * 40 + lane];
            float a1 = g_hl[c1 * 40 + lane];
            float a2 = g_hl[c2 * 40 + lane];
            float a3 = g_hl[c3 * 40 + lane];
            acc0 += (a0 + a1) + (a2 + a3);
            if (lane < 8) {
                float b0 = g_hl[c0 * 40 + 32 + lane];
                float b1 = g_hl[c1 * 40 + 32 + lane];
                float b2 = g_hl[c2 * 40 + 32 + lane];
                float b3 = g_hl[c3 * 40 + 32 + lane];
                acc1 += (b0 + b1) + (b2 + b3);
            }
        }
        for (; jj < cnt; jj++) {
            int c = __shfl_sync(0xffffffffu, myc, jj);
            acc0 += g_hl[c * 40 + lane];
            if (lane < 8) acc1 += g_hl[c * 40 + 32 + lane];
        }
    }
    float inv = 1.0f / (float)max(e - s, 1);
    g_aggl[node * 40 + lane] = acc0 * inv;
    if (lane < 8) g_aggl[node * 40 + 32 + lane] = acc1 * inv;
}

// ---------------- epilogue: relu(aggl + b + hr) -> log_softmax -> transposed out ----------------
__global__ void __launch_bounds__(256) k_out(const float* __restrict__ bl,
                                             float* __restrict__ out) {
    __shared__ float s[40 * 65];
    __shared__ float s_lse[64];
    __shared__ float s_b[40];
    int tid = threadIdx.x;
    int n0 = blockIdx.x * 64;
    int rem = min(64, N_NODES - n0);
    if (tid < 40) s_b[tid] = bl[tid];
    __syncthreads();
    for (int idx = tid; idx < rem * 40; idx += 256) {
        int n = idx / 40, o = idx % 40;
        float v = g_aggl[(n0 + n) * 40 + o] + g_hr[(n0 + n) * 40 + o] + s_b[o];
        s[o * 65 + n] = fmaxf(v, 0.f);
    }
    __syncthreads();
    if (tid < rem) {
        float mx = -1e30f;
        #pragma unroll
        for (int o = 0; o < OUT_DIM; o++) mx = fmaxf(mx, s[o * 65 + tid]);
        float ss = 0.f;
        #pragma unroll
        for (int o = 0; o < OUT_DIM; o++) ss += expf(s[o * 65 + tid] - mx);
        s_lse[tid] = mx + logf(ss);
    }
    __syncthreads();
    for (int idx = tid; idx < 40 * 64; idx += 256) {
        int o = idx >> 6, n = idx & 63;
        if (n < rem) out[o * N_NODES + n0 + n] = s[o * 65 + n] - s_lse[n];
    }
}

// ---------------- launcher ----------------
extern "C" void kernel_launch(void* const* d_in, const int* in_sizes, int n_in,
                              void* d_out, int out_size) {
    const float* x   = (const float*)d_in[0];
    const int*   ei  = (const int*)d_in[1];     // int32 (JAX downcasts int64)
    const float* Wl1 = (const float*)d_in[2];
    const float* bl1 = (const float*)d_in[3];
    const float* Wr1 = (const float*)d_in[4];
    const float* Wl2 = (const float*)d_in[5];
    const float* bl2 = (const float*)d_in[6];
    const float* Wr2 = (const float*)d_in[7];
    float* out = (float*)d_out;

    cudaFuncSetAttribute(k_gemm1, cudaFuncAttributeMaxDynamicSharedMemorySize,
                         G1_SMEM_FLOATS * (int)sizeof(float));
    cudaFuncSetAttribute(k_gemm2ab, cudaFuncAttributeMaxDynamicSharedMemorySize,
                         G2AB_SMEM_FLOATS * (int)sizeof(float));

    k_zero_cnt<<<(N_NODES + 255) / 256, 256>>>();
    k_degree<<<(N_EDGES + 255) / 256, 256>>>(ei);
    k_scan_part<<<NB_SCAN, 1024>>>();
    k_scan_bsum<<<1, 64>>>();
    k_scan_add<<<(N_NODES + 255) / 256, 256>>>();
    k_fill<<<(N_EDGES + 255) / 256, 256>>>(ei);
    k_agg1<<<(N_NODES + 7) / 8, 256>>>(x);
    k_gemm1<<<(N_NODES + 63) / 64, 256, G1_SMEM_FLOATS * sizeof(float)>>>(x, Wl1, bl1, Wr1);
    k_gemm2ab<<<(N_NODES + 63) / 64, 256, G2AB_SMEM_FLOATS * sizeof(float)>>>(Wl2, Wr2);
    k_aggl<<<(N_NODES + 7) / 8, 256>>>();
    k_out<<<(N_NODES + 63) / 64, 256>>>(bl2, out);
}

// round 4
// speedup vs baseline: 1.6666x; 1.0942x over previous
#include <cuda_runtime.h>

#define N_NODES 50000
#define N_EDGES 800000
#define IN_DIM 64
#define HID_DIM 128
#define OUT_DIM 40
#define NB_SCAN 49   // ceil(50000/1024)

// ---------------- scratch (device globals; no allocation) ----------------
__device__ int   g_cnt[N_NODES];
__device__ int   g_rowptr[N_NODES + 1];
__device__ int   g_cursor[N_NODES];
__device__ int   g_col[N_EDGES];
__device__ int   g_bsum[NB_SCAN];
__device__ float g_mean1[N_NODES * IN_DIM];
__device__ float g_hl[N_NODES * OUT_DIM];   // h @ Wl2^T (pre-aggregation)
__device__ float g_hr[N_NODES * OUT_DIM];   // h @ Wr2^T

// ---------------- CSR build ----------------
__global__ void k_zero_cnt() {
    int i = blockIdx.x * blockDim.x + threadIdx.x;
    if (i < N_NODES) g_cnt[i] = 0;
}

__global__ void k_degree(const int* __restrict__ ei) {
    int i = blockIdx.x * blockDim.x + threadIdx.x;
    if (i < N_EDGES) atomicAdd(&g_cnt[ei[N_EDGES + i]], 1);
}

// phase 1: per-block (1024 elems) exclusive scan; block totals to g_bsum
__global__ void __launch_bounds__(1024) k_scan_part() {
    __shared__ int wsum[32];
    int tid = threadIdx.x, lane = tid & 31, warp = tid >> 5;
    int i = blockIdx.x * 1024 + tid;
    int v = (i < N_NODES) ? g_cnt[i] : 0;
    int xs = v;
    #pragma unroll
    for (int off = 1; off < 32; off <<= 1) {
        int t = __shfl_up_sync(0xffffffffu, xs, off);
        if (lane >= off) xs += t;
    }
    if (lane == 31) wsum[warp] = xs;
    __syncthreads();
    if (warp == 0) {
        int s = wsum[lane];
        #pragma unroll
        for (int off = 1; off < 32; off <<= 1) {
            int t = __shfl_up_sync(0xffffffffu, s, off);
            if (lane >= off) s += t;
        }
        wsum[lane] = s;
    }
    __syncthreads();
    int woff = (warp > 0) ? wsum[warp - 1] : 0;
    if (i < N_NODES) g_rowptr[i] = woff + xs - v;   // local exclusive
    if (tid == 1023) g_bsum[blockIdx.x] = woff + xs;
}

// phase 2: add block offsets (each block prefix-sums the 49 totals itself)
__global__ void __launch_bounds__(256) k_scan_add() {
    __shared__ int sb[NB_SCAN];
    int tid = threadIdx.x;
    if (tid < NB_SCAN) sb[tid] = g_bsum[tid];
    __syncthreads();
    int i = blockIdx.x * 256 + tid;
    if (i < N_NODES) {
        int bucket = i >> 10;
        int off = 0;
        for (int b = 0; b < bucket; b++) off += sb[b];
        int r = g_rowptr[i] + off;
        g_rowptr[i] = r;
        g_cursor[i] = r;
    }
    if (i == 0) {
        int tot = 0;
        for (int b = 0; b < NB_SCAN; b++) tot += sb[b];
        g_rowptr[N_NODES] = tot;
    }
}

__global__ void k_fill(const int* __restrict__ ei) {
    int i = blockIdx.x * blockDim.x + threadIdx.x;
    if (i < N_EDGES) {
        int s = ei[i];
        int d = ei[N_EDGES + i];
        g_col[atomicAdd(&g_cursor[d], 1)] = s;
    }
}

// ---------------- layer-1 aggregation: mean over x (64-d), warp/node ----------------
__global__ void k_agg1(const float* __restrict__ x) {
    int node = (blockIdx.x * blockDim.x + threadIdx.x) >> 5;
    int lane = threadIdx.x & 31;
    if (node >= N_NODES) return;
    int s = g_rowptr[node], e = g_rowptr[node + 1];
    const float2* xp = (const float2*)x;
    float2 acc = make_float2(0.f, 0.f);
    for (int base = s; base < e; base += 32) {
        int j = base + lane;
        int myc = (j < e) ? g_col[j] : 0;
        int cnt = min(32, e - base);
        int jj = 0;
        for (; jj + 4 <= cnt; jj += 4) {
            int c0 = __shfl_sync(0xffffffffu, myc, jj);
            int c1 = __shfl_sync(0xffffffffu, myc, jj + 1);
            int c2 = __shfl_sync(0xffffffffu, myc, jj + 2);
            int c3 = __shfl_sync(0xffffffffu, myc, jj + 3);
            float2 v0 = xp[c0 * 32 + lane];
            float2 v1 = xp[c1 * 32 + lane];
            float2 v2 = xp[c2 * 32 + lane];
            float2 v3 = xp[c3 * 32 + lane];
            acc.x += (v0.x + v1.x) + (v2.x + v3.x);
            acc.y += (v0.y + v1.y) + (v2.y + v3.y);
        }
        for (; jj < cnt; jj++) {
            int c = __shfl_sync(0xffffffffu, myc, jj);
            float2 v = xp[c * 32 + lane];
            acc.x += v.x; acc.y += v.y;
        }
    }
    float inv = 1.0f / (float)max(e - s, 1);
    ((float2*)g_mean1)[node * 32 + lane] = make_float2(acc.x * inv, acc.y * inv);
}

// ---------------- fused layer-1 + layer-2 GEMM ----------------
// h = relu(mean1 @ Wl1^T + b1 + x @ Wr1^T) computed into smem (never hits gmem),
// then hl = h @ Wl2^T, hr = h @ Wr2^T written out.
// smem: s_dat[128][65] | s_w 16384 (Wl1|Wr1, later Wl2|Wr2|s_out) | s_b 128
#define G12_SMEM_FLOATS (128 * 65 + 16384 + 128)
__global__ void __launch_bounds__(256) k_gemm12(
    const float* __restrict__ x,
    const float* __restrict__ Wl1, const float* __restrict__ bl1,
    const float* __restrict__ Wr1,
    const float* __restrict__ Wl2, const float* __restrict__ Wr2)
{
    extern __shared__ float sm[];
    float* s_dat = sm;                   // 128*65: inputs k-major, then h o-major
    float* s_w   = sm + 128 * 65;        // 16384
    float* s_b   = s_w + 16384;          // 128
    int tid = threadIdx.x;
    int n0 = blockIdx.x * 64;
    int rem = min(64, N_NODES - n0);

    for (int idx = tid; idx < 8192; idx += 256) {
        s_w[idx] = Wl1[idx];
        s_w[8192 + idx] = Wr1[idx];
    }
    if (tid < 128) s_b[tid] = bl1[tid];

    for (int idx = tid; idx < 64 * 128; idx += 256) {
        int l = idx >> 7, k = idx & 127;
        float v = 0.f;
        if (l < rem) {
            int node = n0 + l;
            v = (k < 64) ? g_mean1[node * 64 + k] : x[node * 64 + (k - 64)];
        }
        s_dat[k * 65 + l] = v;
    }
    __syncthreads();

    // ---- layer 1: 128 outputs, K=64 (dual weights) ----
    int l = tid & 63;
    int obase = (tid >> 6) * 32;
    float acc[32];
    #pragma unroll
    for (int j = 0; j < 32; j++) acc[j] = 0.f;
    {
        const float4* wl4 = (const float4*)s_w;
        const float4* wr4 = (const float4*)(s_w + 8192);
        for (int k = 0; k < 64; k += 4) {
            float m0 = s_dat[(k + 0) * 65 + l];
            float m1 = s_dat[(k + 1) * 65 + l];
            float m2 = s_dat[(k + 2) * 65 + l];
            float m3 = s_dat[(k + 3) * 65 + l];
            float y0 = s_dat[(64 + k + 0) * 65 + l];
            float y1 = s_dat[(64 + k + 1) * 65 + l];
            float y2 = s_dat[(64 + k + 2) * 65 + l];
            float y3 = s_dat[(64 + k + 3) * 65 + l];
            int kq = k >> 2;
            #pragma unroll
            for (int j = 0; j < 32; j++) {
                float4 a = wl4[(obase + j) * 16 + kq];
                float4 b = wr4[(obase + j) * 16 + kq];
                acc[j] += m0 * a.x + m1 * a.y + m2 * a.z + m3 * a.w
                        + y0 * b.x + y1 * b.y + y2 * b.z + y3 * b.w;
            }
        }
    }
    __syncthreads();   // everyone done reading s_dat (inputs) and s_w (layer-1 weights)
    #pragma unroll
    for (int j = 0; j < 32; j++) {
        int o = obase + j;
        s_dat[o * 65 + l] = fmaxf(acc[j] + s_b[o], 0.f);   // h, o-major = k-major for L2
    }
    // overwrite weight region with layer-2 weights
    for (int idx = tid; idx < 5120; idx += 256) {
        s_w[idx] = Wl2[idx];
        s_w[5120 + idx] = Wr2[idx];
    }
    __syncthreads();

    // ---- layer 2: 80 outputs (40 hl + 40 hr), K=128 ----
    int obase2 = (tid >> 6) * 20;
    float acc2[20];
    #pragma unroll
    for (int j = 0; j < 20; j++) acc2[j] = 0.f;
    {
        const float4* w4 = (const float4*)s_w;
        for (int k = 0; k < 128; k += 4) {
            float h0 = s_dat[(k + 0) * 65 + l];
            float h1 = s_dat[(k + 1) * 65 + l];
            float h2 = s_dat[(k + 2) * 65 + l];
            float h3 = s_dat[(k + 3) * 65 + l];
            int kq = k >> 2;
            #pragma unroll
            for (int j = 0; j < 20; j++) {
                float4 a = w4[(obase2 + j) * 32 + kq];
                acc2[j] += h0 * a.x + h1 * a.y + h2 * a.z + h3 * a.w;
            }
        }
    }
    // stage results at s_w+10240 (5200 floats needed, 6144 free) for coalesced writes
    float* s_out = s_w + 10240;
    #pragma unroll
    for (int j = 0; j < 20; j++) s_out[(obase2 + j) * 65 + l] = acc2[j];
    __syncthreads();
    for (int idx = tid; idx < rem * 40; idx += 256) {
        int n = idx / 40, o = idx % 40;
        g_hl[(n0 + n) * 40 + o] = s_out[o * 65 + n];
        g_hr[(n0 + n) * 40 + o] = s_out[(40 + o) * 65 + n];
    }
}

// ---------------- fused layer-2 aggregation + epilogue ----------------
// warp per node: mean-aggregate hl over neighbors, add hr + bias, relu,
// log_softmax over 40 classes via warp reductions, transposed store.
__global__ void k_agglout(const float* __restrict__ bl, float* __restrict__ out) {
    int node = (blockIdx.x * blockDim.x + threadIdx.x) >> 5;
    int lane = threadIdx.x & 31;
    if (node >= N_NODES) return;
    int s = g_rowptr[node], e = g_rowptr[node + 1];
    float acc0 = 0.f, acc1 = 0.f;
    for (int base = s; base < e; base += 32) {
        int j = base + lane;
        int myc = (j < e) ? g_col[j] : 0;
        int cnt = min(32, e - base);
        int jj = 0;
        for (; jj + 4 <= cnt; jj += 4) {
            int c0 = __shfl_sync(0xffffffffu, myc, jj);
            int c1 = __shfl_sync(0xffffffffu, myc, jj + 1);
            int c2 = __shfl_sync(0xffffffffu, myc, jj + 2);
            int c3 = __shfl_sync(0xffffffffu, myc, jj + 3);
            float a0 = g_hl[c0 * 40 + lane];
            float a1 = g_hl[c1 * 40 + lane];
            float a2 = g_hl[c2 * 40 + lane];
            float a3 = g_hl[c3 * 40 + lane];
            acc0 += (a0 + a1) + (a2 + a3);
            if (lane < 8) {
                float b0 = g_hl[c0 * 40 + 32 + lane];
                float b1 = g_hl[c1 * 40 + 32 + lane];
                float b2 = g_hl[c2 * 40 + 32 + lane];
                float b3 = g_hl[c3 * 40 + 32 + lane];
                acc1 += (b0 + b1) + (b2 + b3);
            }
        }
        for (; jj < cnt; jj++) {
            int c = __shfl_sync(0xffffffffu, myc, jj);
            acc0 += g_hl[c * 40 + lane];
            if (lane < 8) acc1 += g_hl[c * 40 + 32 + lane];
        }
    }
    float inv = 1.0f / (float)max(e - s, 1);
    float v0 = fmaxf(acc0 * inv + g_hr[node * 40 + lane] + bl[lane], 0.f);
    float v1 = 0.f;
    if (lane < 8)
        v1 = fmaxf(acc1 * inv + g_hr[node * 40 + 32 + lane] + bl[32 + lane], 0.f);
    // warp-wide max over the 40 values
    float m = fmaxf(v0, (lane < 8) ? v1 : -1e30f);
    #pragma unroll
    for (int off = 16; off > 0; off >>= 1)
        m = fmaxf(m, __shfl_xor_sync(0xffffffffu, m, off));
    // warp-wide sum of exp
    float ssum = expf(v0 - m) + ((lane < 8) ? expf(v1 - m) : 0.f);
    #pragma unroll
    for (int off = 16; off > 0; off >>= 1)
        ssum += __shfl_xor_sync(0xffffffffu, ssum, off);
    float lse = m + logf(ssum);
    out[lane * N_NODES + node] = v0 - lse;
    if (lane < 8) out[(32 + lane) * N_NODES + node] = v1 - lse;
}

// ---------------- launcher ----------------
extern "C" void kernel_launch(void* const* d_in, const int* in_sizes, int n_in,
                              void* d_out, int out_size) {
    const float* x   = (const float*)d_in[0];
    const int*   ei  = (const int*)d_in[1];     // int32 (JAX downcasts int64)
    const float* Wl1 = (const float*)d_in[2];
    const float* bl1 = (const float*)d_in[3];
    const float* Wr1 = (const float*)d_in[4];
    const float* Wl2 = (const float*)d_in[5];
    const float* bl2 = (const float*)d_in[6];
    const float* Wr2 = (const float*)d_in[7];
    float* out = (float*)d_out;

    cudaFuncSetAttribute(k_gemm12, cudaFuncAttributeMaxDynamicSharedMemorySize,
                         G12_SMEM_FLOATS * (int)sizeof(float));

    k_zero_cnt<<<(N_NODES + 255) / 256, 256>>>();
    k_degree<<<(N_EDGES + 255) / 256, 256>>>(ei);
    k_scan_part<<<NB_SCAN, 1024>>>();
    k_scan_add<<<(N_NODES + 255) / 256, 256>>>();
    k_fill<<<(N_EDGES + 255) / 256, 256>>>(ei);
    k_agg1<<<(N_NODES + 7) / 8, 256>>>(x);
    k_gemm12<<<(N_NODES + 63) / 64, 256, G12_SMEM_FLOATS * sizeof(float)>>>(
        x, Wl1, bl1, Wr1, Wl2, Wr2);
    k_agglout<<<(N_NODES + 7) / 8, 256>>>(bl2, out);
}

// round 5
// speedup vs baseline: 1.7477x; 1.0487x over previous
#include <cuda_runtime.h>

#define N_NODES 50000
#define N_EDGES 800000
#define IN_DIM 64
#define HID_DIM 128
#define OUT_DIM 40
#define NB_SCAN 49   // ceil(50000/1024)
#define HL_STRIDE 64 // padded row stride for g_hl (256B aligned)

// ---------------- scratch (device globals; no allocation) ----------------
__device__ int   g_cnt[N_NODES];
__device__ int   g_rowptr[N_NODES + 1];
__device__ int   g_cursor[N_NODES];
__device__ int   g_col[N_EDGES];
__device__ int   g_bsum[NB_SCAN];
__device__ float g_hl[N_NODES * HL_STRIDE]; // h @ Wl2^T (pre-aggregation), padded rows
__device__ float g_hr[N_NODES * OUT_DIM];   // h @ Wr2^T

// ---------------- packed f32x2 helpers ----------------
__device__ __forceinline__ unsigned long long pack2(float v) {
    unsigned long long r;
    asm("mov.b64 %0, {%1, %1};" : "=l"(r) : "f"(v));
    return r;
}
__device__ __forceinline__ void ffma2(unsigned long long& d,
                                      unsigned long long a,
                                      unsigned long long b) {
    asm("fma.rn.f32x2 %0, %1, %2, %0;" : "+l"(d) : "l"(a), "l"(b));
}
__device__ __forceinline__ float2 unpack2(unsigned long long v) {
    float2 r;
    asm("mov.b64 {%0, %1}, %2;" : "=f"(r.x), "=f"(r.y) : "l"(v));
    return r;
}

// ---------------- CSR build ----------------
__global__ void k_zero_cnt() {
    int i = blockIdx.x * blockDim.x + threadIdx.x;
    if (i < N_NODES) g_cnt[i] = 0;
}

__global__ void k_degree(const int* __restrict__ ei) {
    int i = blockIdx.x * blockDim.x + threadIdx.x;
    if (i < N_EDGES) atomicAdd(&g_cnt[ei[N_EDGES + i]], 1);
}

// phase 1: per-block (1024 elems) exclusive scan; block totals to g_bsum
__global__ void __launch_bounds__(1024) k_scan_part() {
    __shared__ int wsum[32];
    int tid = threadIdx.x, lane = tid & 31, warp = tid >> 5;
    int i = blockIdx.x * 1024 + tid;
    int v = (i < N_NODES) ? g_cnt[i] : 0;
    int xs = v;
    #pragma unroll
    for (int off = 1; off < 32; off <<= 1) {
        int t = __shfl_up_sync(0xffffffffu, xs, off);
        if (lane >= off) xs += t;
    }
    if (lane == 31) wsum[warp] = xs;
    __syncthreads();
    if (warp == 0) {
        int s = wsum[lane];
        #pragma unroll
        for (int off = 1; off < 32; off <<= 1) {
            int t = __shfl_up_sync(0xffffffffu, s, off);
            if (lane >= off) s += t;
        }
        wsum[lane] = s;
    }
    __syncthreads();
    int woff = (warp > 0) ? wsum[warp - 1] : 0;
    if (i < N_NODES) g_rowptr[i] = woff + xs - v;   // local exclusive
    if (tid == 1023) g_bsum[blockIdx.x] = woff + xs;
}

// phase 2: add block offsets (each block prefix-sums the 49 totals itself)
__global__ void __launch_bounds__(256) k_scan_add() {
    __shared__ int sb[NB_SCAN];
    int tid = threadIdx.x;
    if (tid < NB_SCAN) sb[tid] = g_bsum[tid];
    __syncthreads();
    int i = blockIdx.x * 256 + tid;
    if (i < N_NODES) {
        int bucket = i >> 10;
        int off = 0;
        for (int b = 0; b < bucket; b++) off += sb[b];
        int r = g_rowptr[i] + off;
        g_rowptr[i] = r;
        g_cursor[i] = r;
    }
    if (i == 0) {
        int tot = 0;
        for (int b = 0; b < NB_SCAN; b++) tot += sb[b];
        g_rowptr[N_NODES] = tot;
    }
}

__global__ void k_fill(const int* __restrict__ ei) {
    int i = blockIdx.x * blockDim.x + threadIdx.x;
    if (i < N_EDGES) {
        int s = ei[i];
        int d = ei[N_EDGES + i];
        g_col[atomicAdd(&g_cursor[d], 1)] = s;
    }
}

// ---------------- fused agg1 + layer-1 + layer-2 GEMM ----------------
// Per 64-node tile:
//   1. warps aggregate neighbor means of x directly into smem (k-major)
//   2. h = relu(mean @ Wl1^T + b1 + x @ Wr1^T) into smem (FFMA2 inner loops)
//   3. hl = h @ Wl2^T, hr = h @ Wr2^T  -> gmem
// smem: s_dat[128][65] | s_w 16384 (packed weights / s_out) | s_b 128
#define G12_SMEM_FLOATS (128 * 65 + 16384 + 128)
__global__ void __launch_bounds__(256) k_gemm12(
    const float* __restrict__ x,
    const float* __restrict__ Wl1, const float* __restrict__ bl1,
    const float* __restrict__ Wr1,
    const float* __restrict__ Wl2, const float* __restrict__ Wr2)
{
    extern __shared__ float sm[];
    float* s_dat = sm;                   // 128*65: [k][node] inputs, then [o][node] h
    float* s_w   = sm + 128 * 65;        // 16384
    float* s_b   = s_w + 16384;          // 128
    int tid = threadIdx.x;
    int n0 = blockIdx.x * 64;
    int rem = min(64, N_NODES - n0);

    // layer-1 weights, FFMA2-packed: float idx = (o>>1)*128 + (k>>1)*4 + (k&1)*2 + (o&1)
    for (int idx = tid; idx < 8192; idx += 256) {
        int o = idx >> 6, k = idx & 63;
        int dst = ((o >> 1) << 7) + ((k >> 1) << 2) + ((k & 1) << 1) + (o & 1);
        s_w[dst] = Wl1[idx];
        s_w[8192 + dst] = Wr1[idx];
    }
    if (tid < 128) s_b[tid] = bl1[tid];

    // x rows (W_r input) -> s_dat[64..128)[node]
    for (int idx = tid; idx < 64 * 64; idx += 256) {
        int l2 = idx >> 6, k = idx & 63;
        float v = (l2 < rem) ? x[(n0 + l2) * 64 + k] : 0.f;
        s_dat[(64 + k) * 65 + l2] = v;
    }

    // neighbor mean of x -> s_dat[0..64)[node]   (warp per node, 8 nodes/warp)
    {
        int warp = tid >> 5, lane = tid & 31;
        const float2* xp = (const float2*)x;
        for (int wn = warp; wn < 64; wn += 8) {
            float2 acc = make_float2(0.f, 0.f);
            int deg = 0;
            if (wn < rem) {
                int node = n0 + wn;
                int s = g_rowptr[node], e = g_rowptr[node + 1];
                deg = e - s;
                for (int base = s; base < e; base += 32) {
                    int j = base + lane;
                    int myc = (j < e) ? g_col[j] : 0;
                    int cnt = min(32, e - base);
                    int jj = 0;
                    for (; jj + 4 <= cnt; jj += 4) {
                        int c0 = __shfl_sync(0xffffffffu, myc, jj);
                        int c1 = __shfl_sync(0xffffffffu, myc, jj + 1);
                        int c2 = __shfl_sync(0xffffffffu, myc, jj + 2);
                        int c3 = __shfl_sync(0xffffffffu, myc, jj + 3);
                        float2 v0 = xp[c0 * 32 + lane];
                        float2 v1 = xp[c1 * 32 + lane];
                        float2 v2 = xp[c2 * 32 + lane];
                        float2 v3 = xp[c3 * 32 + lane];
                        acc.x += (v0.x + v1.x) + (v2.x + v3.x);
                        acc.y += (v0.y + v1.y) + (v2.y + v3.y);
                    }
                    for (; jj < cnt; jj++) {
                        int c = __shfl_sync(0xffffffffu, myc, jj);
                        float2 v = xp[c * 32 + lane];
                        acc.x += v.x; acc.y += v.y;
                    }
                }
            }
            float inv = 1.0f / (float)max(deg, 1);
            s_dat[(2 * lane) * 65 + wn] = acc.x * inv;
            s_dat[(2 * lane + 1) * 65 + wn] = acc.y * inv;
        }
    }
    __syncthreads();

    // ---- layer 1: 128 outputs, K=64 dual weights, FFMA2 ----
    int l = tid & 63;
    int pbase = (tid >> 6) * 16;   // 16 output pairs -> outputs [32*wg, 32*wg+32)
    unsigned long long d1[16];
    #pragma unroll
    for (int p = 0; p < 16; p++) d1[p] = 0ull;
    {
        const ulonglong2* wl = (const ulonglong2*)s_w;            // [P*32 + kk]
        const ulonglong2* wr = (const ulonglong2*)(s_w + 8192);
        for (int kk = 0; kk < 32; kk++) {
            float m0 = s_dat[(2 * kk) * 65 + l];
            float m1 = s_dat[(2 * kk + 1) * 65 + l];
            float y0 = s_dat[(64 + 2 * kk) * 65 + l];
            float y1 = s_dat[(64 + 2 * kk + 1) * 65 + l];
            unsigned long long mm0 = pack2(m0), mm1 = pack2(m1);
            unsigned long long yy0 = pack2(y0), yy1 = pack2(y1);
            #pragma unroll
            for (int p = 0; p < 16; p++) {
                ulonglong2 a = wl[(pbase + p) * 32 + kk];
                ffma2(d1[p], a.x, mm0);
                ffma2(d1[p], a.y, mm1);
                ulonglong2 b = wr[(pbase + p) * 32 + kk];
                ffma2(d1[p], b.x, yy0);
                ffma2(d1[p], b.y, yy1);
            }
        }
    }
    __syncthreads();   // done reading s_dat inputs + layer-1 weights

    // h (+bias, relu) -> s_dat[o][node]  (o-major == k-major for layer 2)
    #pragma unroll
    for (int p = 0; p < 16; p++) {
        int o = 2 * (pbase + p);
        float2 v = unpack2(d1[p]);
        s_dat[o * 65 + l] = fmaxf(v.x + s_b[o], 0.f);
        s_dat[(o + 1) * 65 + l] = fmaxf(v.y + s_b[o + 1], 0.f);
    }
    // layer-2 weights (80 outputs: 40 Wl2 then 40 Wr2), FFMA2-packed:
    // float idx = (o>>1)*256 + (k>>1)*4 + (k&1)*2 + (o&1)
    for (int idx = tid; idx < 5120; idx += 256) {
        int o = idx >> 7, k = idx & 127;
        int dst = ((o >> 1) << 8) + ((k >> 1) << 2) + ((k & 1) << 1) + (o & 1);
        s_w[dst] = Wl2[idx];
        int o2 = o + 40;
        int dst2 = ((o2 >> 1) << 8) + ((k >> 1) << 2) + ((k & 1) << 1) + (o2 & 1);
        s_w[dst2] = Wr2[idx];
    }
    __syncthreads();

    // ---- layer 2: 80 outputs, K=128, FFMA2 ----
    int pbase2 = (tid >> 6) * 10;   // 10 pairs -> outputs [20*wg, 20*wg+20)
    unsigned long long d2[10];
    #pragma unroll
    for (int p = 0; p < 10; p++) d2[p] = 0ull;
    {
        const ulonglong2* w2 = (const ulonglong2*)s_w;    // [P*64 + kk]
        for (int kk = 0; kk < 64; kk++) {
            float h0 = s_dat[(2 * kk) * 65 + l];
            float h1 = s_dat[(2 * kk + 1) * 65 + l];
            unsigned long long hh0 = pack2(h0), hh1 = pack2(h1);
            #pragma unroll
            for (int p = 0; p < 10; p++) {
                ulonglong2 a = w2[(pbase2 + p) * 64 + kk];
                ffma2(d2[p], a.x, hh0);
                ffma2(d2[p], a.y, hh1);
            }
        }
    }
    // stage at s_w+10240 (needs 80*65=5200 <= 6144 free) for coalesced writes
    float* s_out = s_w + 10240;
    #pragma unroll
    for (int p = 0; p < 10; p++) {
        int o = 2 * (pbase2 + p);
        float2 v = unpack2(d2[p]);
        s_out[o * 65 + l] = v.x;
        s_out[(o + 1) * 65 + l] = v.y;
    }
    __syncthreads();
    for (int idx = tid; idx < rem * 40; idx += 256) {
        int n = idx / 40, o = idx % 40;
        g_hl[(n0 + n) * HL_STRIDE + o] = s_out[o * 65 + n];
        g_hr[(n0 + n) * 40 + o] = s_out[(40 + o) * 65 + n];
    }
}

// ---------------- fused layer-2 aggregation + epilogue ----------------
// warp per node: mean-aggregate hl over neighbors, add hr + bias, relu,
// log_softmax over 40 classes via warp reductions, transposed store.
__global__ void k_agglout(const float* __restrict__ bl, float* __restrict__ out) {
    int node = (blockIdx.x * blockDim.x + threadIdx.x) >> 5;
    int lane = threadIdx.x & 31;
    if (node >= N_NODES) return;
    int s = g_rowptr[node], e = g_rowptr[node + 1];
    float acc0 = 0.f, acc1 = 0.f;
    for (int base = s; base < e; base += 32) {
        int j = base + lane;
        int myc = (j < e) ? g_col[j] : 0;
        int cnt = min(32, e - base);
        int jj = 0;
        for (; jj + 4 <= cnt; jj += 4) {
            int c0 = __shfl_sync(0xffffffffu, myc, jj);
            int c1 = __shfl_sync(0xffffffffu, myc, jj + 1);
            int c2 = __shfl_sync(0xffffffffu, myc, jj + 2);
            int c3 = __shfl_sync(0xffffffffu, myc, jj + 3);
            float a0 = g_hl[c0 * HL_STRIDE + lane];
            float a1 = g_hl[c1 * HL_STRIDE + lane];
            float a2 = g_hl[c2 * HL_STRIDE + lane];
            float a3 = g_hl[c3 * HL_STRIDE + lane];
            acc0 += (a0 + a1) + (a2 + a3);
            if (lane < 8) {
                float b0 = g_hl[c0 * HL_STRIDE + 32 + lane];
                float b1 = g_hl[c1 * HL_STRIDE + 32 + lane];
                float b2 = g_hl[c2 * HL_STRIDE + 32 + lane];
                float b3 = g_hl[c3 * HL_STRIDE + 32 + lane];
                acc1 += (b0 + b1) + (b2 + b3);
            }
        }
        for (; jj < cnt; jj++) {
            int c = __shfl_sync(0xffffffffu, myc, jj);
            acc0 += g_hl[c * HL_STRIDE + lane];
            if (lane < 8) acc1 += g_hl[c * HL_STRIDE + 32 + lane];
        }
    }
    float inv = 1.0f / (float)max(e - s, 1);
    float v0 = fmaxf(acc0 * inv + g_hr[node * 40 + lane] + bl[lane], 0.f);
    float v1 = 0.f;
    if (lane < 8)
        v1 = fmaxf(acc1 * inv + g_hr[node * 40 + 32 + lane] + bl[32 + lane], 0.f);
    // warp-wide max over the 40 values
    float m = fmaxf(v0, (lane < 8) ? v1 : -1e30f);
    #pragma unroll
    for (int off = 16; off > 0; off >>= 1)
        m = fmaxf(m, __shfl_xor_sync(0xffffffffu, m, off));
    // warp-wide sum of exp
    float ssum = expf(v0 - m) + ((lane < 8) ? expf(v1 - m) : 0.f);
    #pragma unroll
    for (int off = 16; off > 0; off >>= 1)
        ssum += __shfl_xor_sync(0xffffffffu, ssum, off);
    float lse = m + logf(ssum);
    out[lane * N_NODES + node] = v0 - lse;
    if (lane < 8) out[(32 + lane) * N_NODES + node] = v1 - lse;
}

// ---------------- launcher ----------------
extern "C" void kernel_launch(void* const* d_in, const int* in_sizes, int n_in,
                              void* d_out, int out_size) {
    const float* x   = (const float*)d_in[0];
    const int*   ei  = (const int*)d_in[1];     // int32 (JAX downcasts int64)
    const float* Wl1 = (const float*)d_in[2];
    const float* bl1 = (const float*)d_in[3];
    const float* Wr1 = (const float*)d_in[4];
    const float* Wl2 = (const float*)d_in[5];
    const float* bl2 = (const float*)d_in[6];
    const float* Wr2 = (const float*)d_in[7];
    float* out = (float*)d_out;

    cudaFuncSetAttribute(k_gemm12, cudaFuncAttributeMaxDynamicSharedMemorySize,
                         G12_SMEM_FLOATS * (int)sizeof(float));

    k_zero_cnt<<<(N_NODES + 255) / 256, 256>>>();
    k_degree<<<(N_EDGES + 255) / 256, 256>>>(ei);
    k_scan_part<<<NB_SCAN, 1024>>>();
    k_scan_add<<<(N_NODES + 255) / 256, 256>>>();
    k_fill<<<(N_EDGES + 255) / 256, 256>>>(ei);
    k_gemm12<<<(N_NODES + 63) / 64, 256, G12_SMEM_FLOATS * sizeof(float)>>>(
        x, Wl1, bl1, Wr1, Wl2, Wr2);
    k_agglout<<<(N_NODES + 7) / 8, 256>>>(bl2, out);
}